// round 14
// baseline (speedup 1.0000x reference)
#include <cuda_runtime.h>
#include <cuda_bf16.h>
#include <math.h>

#define NUM_DIRS 720
#define MAXB  8
#define MAXBM (MAXB*3)
#define KA_NT 256
#define MAXS  128               // max slices: supports F <= 32768
#define SLICE_CAP (3*KA_NT)     // 768: max points per slice per measurement
#define KC_NT 768
#define KC_NW (KC_NT/32)
#define SURVCAP 4096            // smem survivor cap in kC (overflow -> exact fallback)

// ---------------- global scratch (static, no allocation, no init needed) ---
// Every element read in a given call is written earlier in the SAME call.
__device__ float2 g_pts[MAXBM][MAXS * SLICE_CAP];  // slice-private regions
__device__ int    g_scnt[MAXBM][MAXS];             // per-slice point counts
__device__ double g_masspart[MAXB][MAXS];

// Edge->plane intersection. Explicit per-op rounding (no FMA contraction) to
// match XLA's unfused elementwise semantics as closely as possible.
__device__ __forceinline__ void edge_point(const float v[9], int e, float h,
                                           bool& valid, float& px, float& pz) {
    int e1 = (e + 1 == 3) ? 0 : e + 1;
    float yi = v[e * 3 + 1], yj = v[e1 * 3 + 1];
    valid = __fmul_rn(__fsub_rn(yi, h), __fsub_rn(yj, h)) < 0.0f;
    float denom = __fsub_rn(yj, yi);
    float safe  = fabsf(denom) > 1e-12f ? denom : 1e-12f;
    float t = fminf(fmaxf(__fdiv_rn(__fsub_rn(h, yi), safe), 0.0f), 1.0f);
    float xi = v[e * 3 + 0], xj = v[e1 * 3 + 0];
    float zi = v[e * 3 + 2], zj = v[e1 * 3 + 2];
    px = __fadd_rn(xi, __fmul_rn(t, __fsub_rn(xj, xi)));
    pz = __fadd_rn(zi, __fmul_rn(t, __fsub_rn(zj, zi)));
}

// Barycentric Y at a face (uniform broadcast loads; per-op rounded)
__device__ __forceinline__ float bary_y(const float* __restrict__ base,
                                        int fidx, const float* __restrict__ bc) {
    const float* tv = base + (size_t)fidx * 9;
    return __fadd_rn(__fadd_rn(__fmul_rn(tv[1], bc[0]),
                               __fmul_rn(tv[4], bc[1])),
                     __fmul_rn(tv[7], bc[2]));
}

// ---------------------------------------------------------------------------
// Kernel 1: face pass. grid (B, nS), 256 threads; slice s owns faces
// [s*256, s*256+256). No global atomics: slice-private output regions.
// ---------------------------------------------------------------------------
__global__ void __launch_bounds__(KA_NT)
kA(const float* __restrict__ tris,
   const float* __restrict__ bc_chest, const float* __restrict__ bc_belly,
   const float* __restrict__ bc_hips,
   const int* __restrict__ i_chest, const int* __restrict__ i_belly,
   const int* __restrict__ i_hips,
   int B, int F) {
    const int b = blockIdx.x, s = blockIdx.y;
    const int tid = threadIdx.x, warp = tid >> 5, lane = tid & 31;
    const unsigned fullm = 0xffffffffu;
    const float* base = tris + (size_t)b * F * 9;

    // plane heights (uniform loads, redundant per thread — trivial)
    const float h0 = bary_y(base, *i_chest, bc_chest);
    const float h1 = bary_y(base, *i_belly, bc_belly);
    const float h2 = bary_y(base, *i_hips,  bc_hips);

    const int f0 = s * KA_NT;
    int nf = F - f0; if (nf > KA_NT) nf = KA_NT; if (nf < 0) nf = 0;

    __shared__ float  sv[KA_NT * 9];        // 9216 B face staging
    __shared__ float2 buf[3][SLICE_CAP];    // 18432 B point buffers
    __shared__ int    bcnt[3];
    __shared__ double md[KA_NT / 32];

    if (tid < 3) bcnt[tid] = 0;
    {
        const float* src = base + (size_t)f0 * 9;
        int nw = nf * 9;
        for (int w = tid; w < nw; w += KA_NT) sv[w] = src[w];   // coalesced
    }
    __syncthreads();

    bool act = tid < nf;
    float v[9];
    int si = (act ? tid : 0) * 9;
#pragma unroll
    for (int q = 0; q < 9; q++) v[q] = sv[si + q];   // stride-9: conflict-free

    double macc = 0.0;
    if (act) {
        float det = -v[6]*v[4]*v[2] + v[3]*v[7]*v[2] + v[6]*v[1]*v[5]
                    - v[0]*v[7]*v[5] - v[3]*v[1]*v[8] + v[0]*v[4]*v[8];
        macc = (double)det;
    }

#pragma unroll
    for (int m = 0; m < 3; m++) {
        float h = (m == 0) ? h0 : (m == 1) ? h1 : h2;
#pragma unroll
        for (int e = 0; e < 3; e++) {
            bool valid; float px, pz;
            edge_point(v, e, h, valid, px, pz);
            valid = valid && act;
            unsigned ball = __ballot_sync(fullm, valid);
            int cnt = __popc(ball);
            if (cnt) {
                int basei = 0;
                if (lane == 0) basei = atomicAdd(&bcnt[m], cnt);  // smem atomic
                basei = __shfl_sync(fullm, basei, 0);
                if (valid) {
                    int pos = basei + __popc(ball & ((1u << lane) - 1u));
                    buf[m][pos] = make_float2(px, pz);            // pos < 768 by construction
                }
            }
        }
    }

    // mass partial
    for (int off = 16; off; off >>= 1) macc += __shfl_down_sync(fullm, macc, off);
    if (lane == 0) md[warp] = macc;
    __syncthreads();

    // flush + counts (no atomics; slice-private region)
    if (tid < 3) g_scnt[b * 3 + tid][s] = bcnt[tid];
#pragma unroll
    for (int m = 0; m < 3; m++) {
        int c = bcnt[m];
        float2* dst = &g_pts[b * 3 + m][s * SLICE_CAP];
        for (int i = tid; i < c; i += KA_NT) dst[i] = buf[m][i];  // coalesced
    }
    if (tid == 0) {
        double sum = 0.0;
        for (int w = 0; w < KA_NT / 32; w++) sum += md[w];
        g_masspart[b][s] = sum;
    }
}

// ---------------------------------------------------------------------------
// Kernel 2 (fused): octant extremes -> polygon -> prune -> 720-dir scan ->
// perimeter. grid (B, 3), 768 threads. Also mass (m==0) + height (m==1).
// ---------------------------------------------------------------------------
__global__ void __launch_bounds__(KC_NT)
kC(const float* __restrict__ tris,
   const float* __restrict__ bc_head, const float* __restrict__ bc_heel,
   const float* __restrict__ bc_chest, const float* __restrict__ bc_belly,
   const float* __restrict__ bc_hips,
   const int* __restrict__ i_head, const int* __restrict__ i_heel,
   const int* __restrict__ i_chest, const int* __restrict__ i_belly,
   const int* __restrict__ i_hips,
   float* __restrict__ out, int B, int F, int nS) {
    const int b = blockIdx.x, m = blockIdx.y, bm = b * 3 + m;
    const int tid = threadIdx.x, warp = tid >> 5, lane = tid & 31;
    const unsigned fullm = 0xffffffffu;
    const float* base = tris + (size_t)b * F * 9;

    __shared__ int    scnt[MAXS];
    __shared__ float  rp[8][KC_NW], rx[8][KC_NW], rz[8][KC_NW];
    __shared__ float4 se[8];
    __shared__ int    s_ne, s_cnt;
    __shared__ float2 surv[SURVCAP];
    __shared__ float  ex[NUM_DIRS], ez[NUM_DIRS];
    __shared__ float  red[KC_NW];

    // per-measurement plane height (uniform loads)
    const float h = (m == 0) ? bary_y(base, *i_chest, bc_chest)
                  : (m == 1) ? bary_y(base, *i_belly, bc_belly)
                             : bary_y(base, *i_hips,  bc_hips);

    // scalar outputs folded in
    if (m == 0 && tid == KC_NT - 1) {
        double sum = 0.0;
        for (int q = 0; q < nS; q++) sum += g_masspart[b][q];
        out[b] = (float)(fabs(sum) / 6.0 * 985.0);
    }
    if (m == 1 && tid == KC_NT - 1) {
        float hy = bary_y(base, *i_head, bc_head);
        float ly = bary_y(base, *i_heel, bc_heel);
        out[B + b] = fabsf(__fsub_rn(hy, ly));
    }

    for (int i = tid; i < nS; i += KC_NT) scnt[i] = g_scnt[bm][i];
    if (tid == 0) s_cnt = 0;
    __syncthreads();

    // ---------- pass 1: 8-dir extremes (warp-per-slice round robin) ---------
    // dirs 0..7 at 45deg; monotone keys {x, x+z, z, z-x, -x, -x-z, -z, x-z}
    float bp[8], bx8[8], bz8[8];
#pragma unroll
    for (int k = 0; k < 8; k++) { bp[k] = -INFINITY; bx8[k] = 0.f; bz8[k] = 0.f; }
    for (int s = warp; s < nS; s += KC_NW) {
        int cnt = scnt[s];
        const float2* sp = &g_pts[bm][s * SLICE_CAP];
        for (int i = lane; i < cnt; i += 32) {
            float2 p = sp[i];
            float u = p.x + p.y, w = p.x - p.y;
            float key[8] = { p.x, u, p.y, -w, -p.x, -u, -p.y, w };
#pragma unroll
            for (int k = 0; k < 8; k++) {
                if (key[k] > bp[k]) { bp[k] = key[k]; bx8[k] = p.x; bz8[k] = p.y; }
            }
        }
    }
#pragma unroll
    for (int k = 0; k < 8; k++) {
        for (int off = 16; off; off >>= 1) {
            float op = __shfl_down_sync(fullm, bp[k], off);
            float ox = __shfl_down_sync(fullm, bx8[k], off);
            float oz = __shfl_down_sync(fullm, bz8[k], off);
            if (op > bp[k]) { bp[k] = op; bx8[k] = ox; bz8[k] = oz; }
        }
    }
    if (lane == 0) {
#pragma unroll
        for (int k = 0; k < 8; k++) { rp[k][warp] = bp[k]; rx[k][warp] = bx8[k]; rz[k][warp] = bz8[k]; }
    }
    __syncthreads();

    // ---------- polygon build (single thread) -------------------------------
    if (tid == 0) {
        float ox[8], oz[8];
        bool anyv = false;
        for (int k = 0; k < 8; k++) {
            float best = -INFINITY, X = 0.f, Z = 0.f;
            for (int w = 0; w < KC_NW; w++) {
                float p = rp[k][w];
                if (p > best) { best = p; X = rx[k][w]; Z = rz[k][w]; }
            }
            ox[k] = X; oz[k] = Z;
            if (k == 0) anyv = (best > -INFINITY);
        }
        int mm = 0; float vx[8], vz[8];
        for (int k = 0; k < 8; k++) {
            float X = ox[k], Z = oz[k];
            if (mm == 0 || X != vx[mm - 1] || Z != vz[mm - 1]) { vx[mm] = X; vz[mm] = Z; mm++; }
        }
        if (mm > 1 && vx[mm - 1] == vx[0] && vz[mm - 1] == vz[0]) mm--;
        if (mm >= 3 && anyv) {
            for (int k = 0; k < mm; k++) {
                int w = (k + 1 == mm) ? 0 : k + 1;
                se[k] = make_float4(vx[w] - vx[k], vz[w] - vz[k], vx[k], vz[k]);
            }
            s_ne = mm;
        } else {
            s_ne = 0;
        }
    }
    __syncthreads();
    const int nedge = s_ne;

    // ---------- pass 2: prune + compact survivors (strictly-inside dropped) -
    for (int s = warp; s < nS; s += KC_NW) {
        int cnt = scnt[s];
        const float2* sp = &g_pts[bm][s * SLICE_CAP];
        for (int i0 = 0; i0 < cnt; i0 += 32) {
            int i = i0 + lane;
            bool act = i < cnt;
            float2 p = act ? sp[i] : make_float2(0.f, 0.f);
            bool keep = act;
            if (act && nedge > 0) {
                bool inside = true;
                for (int k = 0; k < nedge; k++) {
                    float4 E = se[k];
                    float cr = E.x * (p.y - E.w) - E.y * (p.x - E.z);
                    inside = inside && (cr > 0.0f);
                }
                keep = !inside;
            }
            unsigned ball = __ballot_sync(fullm, keep);
            int cntk = __popc(ball);
            if (cntk) {
                int basei = 0;
                if (lane == 0) basei = atomicAdd(&s_cnt, cntk);  // smem atomic
                basei = __shfl_sync(fullm, basei, 0);
                if (keep) {
                    int pos = basei + __popc(ball & ((1u << lane) - 1u));
                    if (pos < SURVCAP) surv[pos] = p;
                }
            }
        }
    }
    __syncthreads();
    const int ns = s_cnt;

    // ---------- pass 3: 720-direction scan ----------------------------------
    float dc = 0.f, ds = 0.f;
    if (tid < NUM_DIRS) {
        float theta = (float)tid * (float)(6.283185307179586 / 720.0);
        dc = (float)cos((double)theta);
        ds = (float)sin((double)theta);
    }
    // fallback = candidate 0's point (reference: argmax of all -inf -> idx 0)
    float v[9];
#pragma unroll
    for (int q = 0; q < 9; q++) v[q] = base[q];
    bool dmy; float fx, fz;
    edge_point(v, 0, h, dmy, fx, fz);

    float best = -INFINITY, bestx = fx, bestz = fz;
    if (tid < NUM_DIRS) {
        if (ns <= SURVCAP) {
            for (int i = 0; i < ns; i++) {
                float2 p = surv[i];                 // smem broadcast
                float pr = __fadd_rn(__fmul_rn(p.x, dc), __fmul_rn(p.y, ds));
                if (pr > best) { best = pr; bestx = p.x; bestz = p.y; }
            }
        } else {
            // exact fallback: unpruned argmax over all stored points
            for (int s = 0; s < nS; s++) {
                int cnt = scnt[s];
                const float2* sp = &g_pts[bm][s * SLICE_CAP];
                for (int i = 0; i < cnt; i++) {
                    float2 p = sp[i];
                    float pr = __fadd_rn(__fmul_rn(p.x, dc), __fmul_rn(p.y, ds));
                    if (pr > best) { best = pr; bestx = p.x; bestz = p.y; }
                }
            }
        }
        ex[tid] = bestx; ez[tid] = bestz;
    }
    __syncthreads();

    // ---------- perimeter ----------------------------------------------------
    float seg = 0.f;
    if (tid < NUM_DIRS) {
        int nx = (tid + 1 == NUM_DIRS) ? 0 : tid + 1;
        float dx = __fsub_rn(ex[tid], ex[nx]);
        float dz = __fsub_rn(ez[tid], ez[nx]);
        seg = sqrtf(__fadd_rn(__fadd_rn(__fmul_rn(dx, dx), __fmul_rn(dz, dz)), 1e-20f));
    }
    for (int off = 16; off; off >>= 1) seg += __shfl_down_sync(fullm, seg, off);
    if (lane == 0) red[warp] = seg;
    __syncthreads();
    if (tid == 0) {
        float s = 0.f;
        for (int w = 0; w < KC_NW; w++) s += red[w];
        out[(2 + m) * B + b] = s;
    }
}

// ---------------------------------------------------------------------------
extern "C" void kernel_launch(void* const* d_in, const int* in_sizes, int n_in,
                              void* d_out, int out_size) {
    const float* tris     = (const float*)d_in[0];
    const float* bc_head  = (const float*)d_in[1];
    const float* bc_heel  = (const float*)d_in[2];
    const float* bc_chest = (const float*)d_in[3];
    const float* bc_belly = (const float*)d_in[4];
    const float* bc_hips  = (const float*)d_in[5];
    const int*   i_head   = (const int*)d_in[6];
    const int*   i_heel   = (const int*)d_in[7];
    const int*   i_chest  = (const int*)d_in[8];
    const int*   i_belly  = (const int*)d_in[9];
    const int*   i_hips   = (const int*)d_in[10];
    float* out = (float*)d_out;

    int B = out_size / 5;
    int F = in_sizes[0] / (9 * B);
    int nS = (F + KA_NT - 1) / KA_NT;
    if (nS < 1) nS = 1;
    if (nS > MAXS) nS = MAXS;   // F beyond 32768 unsupported by scratch sizing

    kA<<<dim3(B, nS), KA_NT>>>(tris, bc_chest, bc_belly, bc_hips,
                               i_chest, i_belly, i_hips, B, F);
    kC<<<dim3(B, 3), KC_NT>>>(tris, bc_head, bc_heel, bc_chest, bc_belly, bc_hips,
                              i_head, i_heel, i_chest, i_belly, i_hips,
                              out, B, F, nS);
}

// round 15
// speedup vs baseline: 1.1347x; 1.1347x over previous
#include <cuda_runtime.h>
#include <cuda_bf16.h>
#include <math.h>

#define NUM_DIRS 720
#define MAXB  8
#define MAXBM (MAXB*3)
#define KA_NT 256
#define MAXS  128               // max slices: supports F <= 32768
#define SLICE_CAP (3*KA_NT)     // 768: max points per slice per measurement
#define KC_NT 768
#define KC_NW (KC_NT/32)
#define SURVCAP 4096            // smem survivor cap in kC (overflow -> exact fallback)

// ---------------- global scratch (static, no allocation, no init needed) ---
// Every element read in a given call is written earlier in the SAME call.
__device__ float2 g_pts[MAXBM][MAXS * SLICE_CAP];  // slice-private regions
__device__ int    g_scnt[MAXBM][MAXS];             // per-slice point counts
__device__ double g_masspart[MAXB][MAXS];

// Edge->plane intersection. Explicit per-op rounding (no FMA contraction) to
// match XLA's unfused elementwise semantics as closely as possible.
__device__ __forceinline__ void edge_point(const float v[9], int e, float h,
                                           bool& valid, float& px, float& pz) {
    int e1 = (e + 1 == 3) ? 0 : e + 1;
    float yi = v[e * 3 + 1], yj = v[e1 * 3 + 1];
    valid = __fmul_rn(__fsub_rn(yi, h), __fsub_rn(yj, h)) < 0.0f;
    float denom = __fsub_rn(yj, yi);
    float safe  = fabsf(denom) > 1e-12f ? denom : 1e-12f;
    float t = fminf(fmaxf(__fdiv_rn(__fsub_rn(h, yi), safe), 0.0f), 1.0f);
    float xi = v[e * 3 + 0], xj = v[e1 * 3 + 0];
    float zi = v[e * 3 + 2], zj = v[e1 * 3 + 2];
    px = __fadd_rn(xi, __fmul_rn(t, __fsub_rn(xj, xi)));
    pz = __fadd_rn(zi, __fmul_rn(t, __fsub_rn(zj, zi)));
}

// Barycentric Y at a face (uniform broadcast loads; per-op rounded)
__device__ __forceinline__ float bary_y(const float* __restrict__ base,
                                        int fidx, const float* __restrict__ bc) {
    const float* tv = base + (size_t)fidx * 9;
    return __fadd_rn(__fadd_rn(__fmul_rn(tv[1], bc[0]),
                               __fmul_rn(tv[4], bc[1])),
                     __fmul_rn(tv[7], bc[2]));
}

// ---------------------------------------------------------------------------
// Kernel 1: face pass. grid (B, nS), 256 threads; slice s owns faces
// [s*256, s*256+256). No global atomics: slice-private output regions.
// ---------------------------------------------------------------------------
__global__ void __launch_bounds__(KA_NT)
kA(const float* __restrict__ tris,
   const float* __restrict__ bc_chest, const float* __restrict__ bc_belly,
   const float* __restrict__ bc_hips,
   const int* __restrict__ i_chest, const int* __restrict__ i_belly,
   const int* __restrict__ i_hips,
   int B, int F) {
    const int b = blockIdx.x, s = blockIdx.y;
    const int tid = threadIdx.x, warp = tid >> 5, lane = tid & 31;
    const unsigned fullm = 0xffffffffu;
    const float* base = tris + (size_t)b * F * 9;

    // plane heights (uniform loads, redundant per thread — trivial)
    const float h0 = bary_y(base, *i_chest, bc_chest);
    const float h1 = bary_y(base, *i_belly, bc_belly);
    const float h2 = bary_y(base, *i_hips,  bc_hips);

    const int f0 = s * KA_NT;
    int nf = F - f0; if (nf > KA_NT) nf = KA_NT; if (nf < 0) nf = 0;

    __shared__ float  sv[KA_NT * 9];        // 9216 B face staging
    __shared__ float2 buf[3][SLICE_CAP];    // 18432 B point buffers
    __shared__ int    bcnt[3];
    __shared__ double md[KA_NT / 32];

    if (tid < 3) bcnt[tid] = 0;
    {
        const float* src = base + (size_t)f0 * 9;
        int nw = nf * 9;
        for (int w = tid; w < nw; w += KA_NT) sv[w] = src[w];   // coalesced
    }
    __syncthreads();

    bool act = tid < nf;
    float v[9];
    int si = (act ? tid : 0) * 9;
#pragma unroll
    for (int q = 0; q < 9; q++) v[q] = sv[si + q];   // stride-9: conflict-free

    double macc = 0.0;
    if (act) {
        float det = -v[6]*v[4]*v[2] + v[3]*v[7]*v[2] + v[6]*v[1]*v[5]
                    - v[0]*v[7]*v[5] - v[3]*v[1]*v[8] + v[0]*v[4]*v[8];
        macc = (double)det;
    }

#pragma unroll
    for (int m = 0; m < 3; m++) {
        float h = (m == 0) ? h0 : (m == 1) ? h1 : h2;
#pragma unroll
        for (int e = 0; e < 3; e++) {
            bool valid; float px, pz;
            edge_point(v, e, h, valid, px, pz);
            valid = valid && act;
            unsigned ball = __ballot_sync(fullm, valid);
            int cnt = __popc(ball);
            if (cnt) {
                int basei = 0;
                if (lane == 0) basei = atomicAdd(&bcnt[m], cnt);  // smem atomic
                basei = __shfl_sync(fullm, basei, 0);
                if (valid) {
                    int pos = basei + __popc(ball & ((1u << lane) - 1u));
                    buf[m][pos] = make_float2(px, pz);            // pos < 768 by construction
                }
            }
        }
    }

    // mass partial
    for (int off = 16; off; off >>= 1) macc += __shfl_down_sync(fullm, macc, off);
    if (lane == 0) md[warp] = macc;
    __syncthreads();

    // flush + counts (no atomics; slice-private region)
    if (tid < 3) g_scnt[b * 3 + tid][s] = bcnt[tid];
#pragma unroll
    for (int m = 0; m < 3; m++) {
        int c = bcnt[m];
        float2* dst = &g_pts[b * 3 + m][s * SLICE_CAP];
        for (int i = tid; i < c; i += KA_NT) dst[i] = buf[m][i];  // coalesced
    }
    if (tid == 0) {
        double sum = 0.0;
        for (int w = 0; w < KA_NT / 32; w++) sum += md[w];
        g_masspart[b][s] = sum;
    }
}

// ---------------------------------------------------------------------------
// Kernel 2 (fused): octant extremes -> polygon -> prune -> 720-dir scan ->
// perimeter. grid (B, 3), 768 threads. Also mass (m==0) + height (m==1).
// ---------------------------------------------------------------------------
__global__ void __launch_bounds__(KC_NT)
kC(const float* __restrict__ tris,
   const float* __restrict__ bc_head, const float* __restrict__ bc_heel,
   const float* __restrict__ bc_chest, const float* __restrict__ bc_belly,
   const float* __restrict__ bc_hips,
   const int* __restrict__ i_head, const int* __restrict__ i_heel,
   const int* __restrict__ i_chest, const int* __restrict__ i_belly,
   const int* __restrict__ i_hips,
   float* __restrict__ out, int B, int F, int nS) {
    const int b = blockIdx.x, m = blockIdx.y, bm = b * 3 + m;
    const int tid = threadIdx.x, warp = tid >> 5, lane = tid & 31;
    const unsigned fullm = 0xffffffffu;
    const float* base = tris + (size_t)b * F * 9;

    __shared__ int    scnt[MAXS];
    __shared__ float  rp[8][KC_NW], rx[8][KC_NW], rz[8][KC_NW];
    __shared__ float4 se[8];
    __shared__ int    s_ne, s_cnt;
    __shared__ float2 surv[SURVCAP];
    __shared__ float  ex[NUM_DIRS], ez[NUM_DIRS];
    __shared__ float  red[KC_NW];

    // per-measurement plane height (uniform loads)
    const float h = (m == 0) ? bary_y(base, *i_chest, bc_chest)
                  : (m == 1) ? bary_y(base, *i_belly, bc_belly)
                             : bary_y(base, *i_hips,  bc_hips);

    // scalar outputs folded in
    if (m == 0 && tid == KC_NT - 1) {
        double sum = 0.0;
        for (int q = 0; q < nS; q++) sum += g_masspart[b][q];
        out[b] = (float)(fabs(sum) / 6.0 * 985.0);
    }
    if (m == 1 && tid == KC_NT - 1) {
        float hy = bary_y(base, *i_head, bc_head);
        float ly = bary_y(base, *i_heel, bc_heel);
        out[B + b] = fabsf(__fsub_rn(hy, ly));
    }

    for (int i = tid; i < nS; i += KC_NT) scnt[i] = g_scnt[bm][i];
    if (tid == 0) s_cnt = 0;
    __syncthreads();

    // ---------- pass 1: 8-dir extremes (warp-per-slice round robin) ---------
    // dirs 0..7 at 45deg; monotone keys {x, x+z, z, z-x, -x, -x-z, -z, x-z}
    float bp[8], bx8[8], bz8[8];
#pragma unroll
    for (int k = 0; k < 8; k++) { bp[k] = -INFINITY; bx8[k] = 0.f; bz8[k] = 0.f; }
    for (int s = warp; s < nS; s += KC_NW) {
        int cnt = scnt[s];
        const float2* sp = &g_pts[bm][s * SLICE_CAP];
        for (int i = lane; i < cnt; i += 32) {
            float2 p = sp[i];
            float u = p.x + p.y, w = p.x - p.y;
            float key[8] = { p.x, u, p.y, -w, -p.x, -u, -p.y, w };
#pragma unroll
            for (int k = 0; k < 8; k++) {
                if (key[k] > bp[k]) { bp[k] = key[k]; bx8[k] = p.x; bz8[k] = p.y; }
            }
        }
    }
#pragma unroll
    for (int k = 0; k < 8; k++) {
        for (int off = 16; off; off >>= 1) {
            float op = __shfl_down_sync(fullm, bp[k], off);
            float ox = __shfl_down_sync(fullm, bx8[k], off);
            float oz = __shfl_down_sync(fullm, bz8[k], off);
            if (op > bp[k]) { bp[k] = op; bx8[k] = ox; bz8[k] = oz; }
        }
    }
    if (lane == 0) {
#pragma unroll
        for (int k = 0; k < 8; k++) { rp[k][warp] = bp[k]; rx[k][warp] = bx8[k]; rz[k][warp] = bz8[k]; }
    }
    __syncthreads();

    // ---------- polygon build (single thread) -------------------------------
    if (tid == 0) {
        float ox[8], oz[8];
        bool anyv = false;
        for (int k = 0; k < 8; k++) {
            float best = -INFINITY, X = 0.f, Z = 0.f;
            for (int w = 0; w < KC_NW; w++) {
                float p = rp[k][w];
                if (p > best) { best = p; X = rx[k][w]; Z = rz[k][w]; }
            }
            ox[k] = X; oz[k] = Z;
            if (k == 0) anyv = (best > -INFINITY);
        }
        int mm = 0; float vx[8], vz[8];
        for (int k = 0; k < 8; k++) {
            float X = ox[k], Z = oz[k];
            if (mm == 0 || X != vx[mm - 1] || Z != vz[mm - 1]) { vx[mm] = X; vz[mm] = Z; mm++; }
        }
        if (mm > 1 && vx[mm - 1] == vx[0] && vz[mm - 1] == vz[0]) mm--;
        if (mm >= 3 && anyv) {
            for (int k = 0; k < mm; k++) {
                int w = (k + 1 == mm) ? 0 : k + 1;
                se[k] = make_float4(vx[w] - vx[k], vz[w] - vz[k], vx[k], vz[k]);
            }
            s_ne = mm;
        } else {
            s_ne = 0;
        }
    }
    __syncthreads();
    const int nedge = s_ne;

    // ---------- pass 2: prune + compact survivors (strictly-inside dropped) -
    for (int s = warp; s < nS; s += KC_NW) {
        int cnt = scnt[s];
        const float2* sp = &g_pts[bm][s * SLICE_CAP];
        for (int i0 = 0; i0 < cnt; i0 += 32) {
            int i = i0 + lane;
            bool act = i < cnt;
            float2 p = act ? sp[i] : make_float2(0.f, 0.f);
            bool keep = act;
            if (act && nedge > 0) {
                bool inside = true;
                for (int k = 0; k < nedge; k++) {
                    float4 E = se[k];
                    float cr = E.x * (p.y - E.w) - E.y * (p.x - E.z);
                    inside = inside && (cr > 0.0f);
                }
                keep = !inside;
            }
            unsigned ball = __ballot_sync(fullm, keep);
            int cntk = __popc(ball);
            if (cntk) {
                int basei = 0;
                if (lane == 0) basei = atomicAdd(&s_cnt, cntk);  // smem atomic
                basei = __shfl_sync(fullm, basei, 0);
                if (keep) {
                    int pos = basei + __popc(ball & ((1u << lane) - 1u));
                    if (pos < SURVCAP) surv[pos] = p;
                }
            }
        }
    }
    __syncthreads();
    const int ns = s_cnt;

    // ---------- pass 3: 720-direction scan ----------------------------------
    // fp32 trig: matches XLA's f32 cos/sin to ~1e-7. Argmax flips can occur
    // only at hull-transition boundary directions where consecutive extremes
    // change {p,p,q}->{p,q,q}; both give segment sum |p-q| -> perimeter-neutral.
    float dc = 0.f, ds = 0.f;
    if (tid < NUM_DIRS) {
        float theta = (float)tid * (float)(6.283185307179586 / 720.0);
        dc = cosf(theta);
        ds = sinf(theta);
    }
    // fallback = candidate 0's point (reference: argmax of all -inf -> idx 0)
    float v[9];
#pragma unroll
    for (int q = 0; q < 9; q++) v[q] = base[q];
    bool dmy; float fx, fz;
    edge_point(v, 0, h, dmy, fx, fz);

    float best = -INFINITY, bestx = fx, bestz = fz;
    if (tid < NUM_DIRS) {
        if (ns <= SURVCAP) {
            for (int i = 0; i < ns; i++) {
                float2 p = surv[i];                 // smem broadcast
                float pr = __fadd_rn(__fmul_rn(p.x, dc), __fmul_rn(p.y, ds));
                if (pr > best) { best = pr; bestx = p.x; bestz = p.y; }
            }
        } else {
            // exact fallback: unpruned argmax over all stored points
            for (int s = 0; s < nS; s++) {
                int cnt = scnt[s];
                const float2* sp = &g_pts[bm][s * SLICE_CAP];
                for (int i = 0; i < cnt; i++) {
                    float2 p = sp[i];
                    float pr = __fadd_rn(__fmul_rn(p.x, dc), __fmul_rn(p.y, ds));
                    if (pr > best) { best = pr; bestx = p.x; bestz = p.y; }
                }
            }
        }
        ex[tid] = bestx; ez[tid] = bestz;
    }
    __syncthreads();

    // ---------- perimeter ----------------------------------------------------
    float seg = 0.f;
    if (tid < NUM_DIRS) {
        int nx = (tid + 1 == NUM_DIRS) ? 0 : tid + 1;
        float dx = __fsub_rn(ex[tid], ex[nx]);
        float dz = __fsub_rn(ez[tid], ez[nx]);
        seg = sqrtf(__fadd_rn(__fadd_rn(__fmul_rn(dx, dx), __fmul_rn(dz, dz)), 1e-20f));
    }
    for (int off = 16; off; off >>= 1) seg += __shfl_down_sync(fullm, seg, off);
    if (lane == 0) red[warp] = seg;
    __syncthreads();
    if (tid == 0) {
        float s = 0.f;
        for (int w = 0; w < KC_NW; w++) s += red[w];
        out[(2 + m) * B + b] = s;
    }
}

// ---------------------------------------------------------------------------
extern "C" void kernel_launch(void* const* d_in, const int* in_sizes, int n_in,
                              void* d_out, int out_size) {
    const float* tris     = (const float*)d_in[0];
    const float* bc_head  = (const float*)d_in[1];
    const float* bc_heel  = (const float*)d_in[2];
    const float* bc_chest = (const float*)d_in[3];
    const float* bc_belly = (const float*)d_in[4];
    const float* bc_hips  = (const float*)d_in[5];
    const int*   i_head   = (const int*)d_in[6];
    const int*   i_heel   = (const int*)d_in[7];
    const int*   i_chest  = (const int*)d_in[8];
    const int*   i_belly  = (const int*)d_in[9];
    const int*   i_hips   = (const int*)d_in[10];
    float* out = (float*)d_out;

    int B = out_size / 5;
    int F = in_sizes[0] / (9 * B);
    int nS = (F + KA_NT - 1) / KA_NT;
    if (nS < 1) nS = 1;
    if (nS > MAXS) nS = MAXS;   // F beyond 32768 unsupported by scratch sizing

    kA<<<dim3(B, nS), KA_NT>>>(tris, bc_chest, bc_belly, bc_hips,
                               i_chest, i_belly, i_hips, B, F);
    kC<<<dim3(B, 3), KC_NT>>>(tris, bc_head, bc_heel, bc_chest, bc_belly, bc_hips,
                              i_head, i_heel, i_chest, i_belly, i_hips,
                              out, B, F, nS);
}